// round 11
// baseline (speedup 1.0000x reference)
#include <cuda_runtime.h>

// Problem constants
#define B_   64
#define C_   256
#define HW_  4096
#define EMB_ 512
#define BT   2                               // batches per stage1 warp-task
#define NTASK (C_ * (B_ / BT))               // 8192 stage1 tasks
#define STG_BLOCKS (NTASK / 8)               // 1024 blocks x 8 warps (R7-proven)
#define W3_BLOCKS 256                        // 64 i-tiles x 4 j-tiles
#define K1_BLOCKS (W3_BLOCKS + STG_BLOCKS)   // 1280

// Scratch (allocation-free rule: __device__ globals)
__device__ float g_t1[B_ * C_];   // t1[b] = kv_w_v @ ce[b] + kv_b_v
__device__ float g_W3[C_ * C_];   // W3 = out_w @ wv           (row-major by c)
__device__ float g_d3[C_];        // d3 = out_w @ bv + out_b

// ---------------------------------------------------------------------------
// K1: two independent roles packed into one grid.
//  bid <  W3_BLOCKS : W3 4x64 tile (smem-staged out_w, coalesced wv stream)
//  bid >= W3_BLOCKS : stage1, R7-proven geometry (one warp per (row, b-pair))
// ---------------------------------------------------------------------------
__global__ void __launch_bounds__(256) pre_kernel(
    const float* __restrict__ cond_emb,    // (B, EMB)
    const float* __restrict__ in_proj_w,   // (3C, C): wv = rows [2C,3C)
    const float* __restrict__ in_proj_b,   // (3C,):   bv = [2C,3C)
    const float* __restrict__ out_w,       // (C, C)
    const float* __restrict__ out_b,       // (C,)
    const float* __restrict__ kv_w,        // (2C, EMB): v-part = rows [C,2C)
    const float* __restrict__ kv_b)        // (2C,)
{
    const int bid  = blockIdx.x;
    const int tid  = threadIdx.x;
    const int lane = tid & 31;
    const int warp = tid >> 5;

    if (bid < W3_BLOCKS) {
        // ---- W3 tile: rows [i0,i0+4), cols [j0,j0+64) ----
        const int it = bid & 63, jt = bid >> 6;
        const int i0 = it * 4, j0 = jt * 64;
        const int isub = tid >> 6;          // 0..3
        const int jl   = tid & 63;          // 0..63

        __shared__ float s_ow[4][C_];       // out_w tile, 4KB
        #pragma unroll
        for (int rr = 0; rr < 4; rr++)
            s_ow[rr][tid] = out_w[(size_t)(i0 + rr) * C_ + tid];
        __syncthreads();

        const float* __restrict__ wv = in_proj_w + (size_t)2 * C_ * C_;

        float acc = 0.f;
        #pragma unroll 16
        for (int k = 0; k < C_; k++)
            acc += s_ow[isub][k] * wv[(size_t)k * C_ + j0 + jl];   // coalesced 64-wide
        g_W3[(size_t)(i0 + isub) * C_ + j0 + jl] = acc;

        // ---- d3 (only j-tile 0 blocks; warps 0..3, one row each) ----
        if (jt == 0 && warp < 4) {
            const float* __restrict__ bv = in_proj_b + 2 * C_;
            float p = 0.f;
            #pragma unroll
            for (int k = lane; k < C_; k += 32)
                p += s_ow[warp][k] * bv[k];
            #pragma unroll
            for (int o = 16; o > 0; o >>= 1)
                p += __shfl_down_sync(0xffffffffu, p, o);
            if (lane == 0)
                g_d3[i0 + warp] = p + out_b[i0 + warp];
        }
    } else {
        // ---- stage1: t1[(b0+j)][r] = dot(kv_w_v[r], ce[b0+j]) + kv_b_v[r] ----
        const int gw = (bid - W3_BLOCKS) * 8 + warp;   // 0 .. NTASK-1
        const int r  = gw & (C_ - 1);
        const int b0 = (gw >> 8) * BT;

        const float4* __restrict__ wrow =
            reinterpret_cast<const float4*>(kv_w + (size_t)(C_ + r) * EMB_);
        const float4* __restrict__ xin =
            reinterpret_cast<const float4*>(cond_emb + (size_t)b0 * EMB_);

        float acc0 = 0.f, acc1 = 0.f;
        #pragma unroll
        for (int k = lane; k < EMB_ / 4; k += 32) {
            const float4 a  = wrow[k];
            const float4 c0 = xin[k];
            const float4 c1 = xin[(EMB_ / 4) + k];
            acc0 += a.x * c0.x + a.y * c0.y + a.z * c0.z + a.w * c0.w;
            acc1 += a.x * c1.x + a.y * c1.y + a.z * c1.z + a.w * c1.w;
        }
        #pragma unroll
        for (int o = 16; o > 0; o >>= 1) {
            acc0 += __shfl_down_sync(0xffffffffu, acc0, o);
            acc1 += __shfl_down_sync(0xffffffffu, acc1, o);
        }
        if (lane == 0) {
            const float bs = kv_b[C_ + r];
            g_t1[(size_t)b0 * C_ + r]       = acc0 + bs;
            g_t1[(size_t)(b0 + 1) * C_ + r] = acc1 + bs;
        }
    }
}

// ---------------------------------------------------------------------------
// K2: stream kernel with inline final projection (R7-proven smem-reduce form):
//   a       = dot(W3[c,:], t1[b,:]) + d3[c]
//   y[bc,:] = x[bc,:] + a
// ---------------------------------------------------------------------------
__global__ void __launch_bounds__(256) broadcast_add_kernel(
    const float* __restrict__ x,
    float* __restrict__ y)
{
    const int bc   = blockIdx.x;                 // 0 .. B*C-1
    const int b    = bc >> 8;
    const int c    = bc & (C_ - 1);
    const int tid  = threadIdx.x;
    const int lane = tid & 31;
    const int warp = tid >> 5;

    const float4* __restrict__ xi = reinterpret_cast<const float4*>(x) + (size_t)bc * (HW_ / 4);
    float4* __restrict__       yo = reinterpret_cast<float4*>(y)       + (size_t)bc * (HW_ / 4);

    // Streaming loads first; the dot hides beneath them.
    float4 v0 = xi[tid];
    float4 v1 = xi[tid + 256];
    float4 v2 = xi[tid + 512];
    float4 v3 = xi[tid + 768];

    float p = g_W3[(size_t)c * C_ + tid] * g_t1[(size_t)b * C_ + tid];
    #pragma unroll
    for (int o = 16; o > 0; o >>= 1)
        p += __shfl_down_sync(0xffffffffu, p, o);

    __shared__ float s_part[8];
    __shared__ float s_a;
    if (lane == 0) s_part[warp] = p;
    __syncthreads();
    if (tid < 8) {
        float q = s_part[tid];
        q += __shfl_down_sync(0x000000ffu, q, 4);
        q += __shfl_down_sync(0x000000ffu, q, 2);
        q += __shfl_down_sync(0x000000ffu, q, 1);
        if (tid == 0) s_a = q + g_d3[c];
    }
    __syncthreads();
    const float a = s_a;

    v0.x += a; v0.y += a; v0.z += a; v0.w += a;
    v1.x += a; v1.y += a; v1.z += a; v1.w += a;
    v2.x += a; v2.y += a; v2.z += a; v2.w += a;
    v3.x += a; v3.y += a; v3.z += a; v3.w += a;
    yo[tid]       = v0;
    yo[tid + 256] = v1;
    yo[tid + 512] = v2;
    yo[tid + 768] = v3;
}

extern "C" void kernel_launch(void* const* d_in, const int* in_sizes, int n_in,
                              void* d_out, int out_size)
{
    // metadata order: x, cond_emb, ln_gamma, ln_beta, in_proj_w, in_proj_b,
    //                 out_w, out_b, kv_w, kv_b
    const float* x         = (const float*)d_in[0];
    const float* cond_emb  = (const float*)d_in[1];
    // ln_gamma/ln_beta provably do not affect the output: softmax over the
    // size-1 KV axis is exactly 1, so q (and thus x_ln) cancels.
    const float* in_proj_w = (const float*)d_in[4];
    const float* in_proj_b = (const float*)d_in[5];
    const float* out_w     = (const float*)d_in[6];
    const float* out_b     = (const float*)d_in[7];
    const float* kv_w      = (const float*)d_in[8];
    const float* kv_b      = (const float*)d_in[9];
    float* y = (float*)d_out;

    pre_kernel<<<K1_BLOCKS, 256>>>(cond_emb, in_proj_w, in_proj_b,
                                   out_w, out_b, kv_w, kv_b);
    broadcast_add_kernel<<<B_ * C_, 256>>>(x, y);
}

// round 12
// speedup vs baseline: 1.1304x; 1.1304x over previous
#include <cuda_runtime.h>

// Problem constants
#define B_   64
#define C_   256
#define HW_  4096
#define EMB_ 512
#define CLUSTER 8                    // blocks per cluster; 1 cluster = 1 batch
#define CHAIN_BLOCKS (B_ * CLUSTER)  // 512

// Scratch (allocation-free rule: __device__ globals)
__device__ float g_t1[B_ * C_];
__device__ float g_t2[B_ * C_];

// ---------------------------------------------------------------------------
// K1: stage1 + stage2 in ONE launch, synchronized by the HW cluster barrier.
// Cluster c (8 blocks x 256 thr = 64 warps) owns batch b = c.
//   stage1: warp w computes t1[b][4w..4w+3]  (512-dots)
//   barrier.cluster (HW, co-residency guaranteed -> no deadlock possible)
//   stage2: warp w computes t2[b][4w..4w+3]  (256-dots over t1[b], L2 reads)
// ---------------------------------------------------------------------------
__global__ void __launch_bounds__(256) __cluster_dims__(CLUSTER, 1, 1)
chain_cluster_kernel(
    const float* __restrict__ cond_emb,    // (B, EMB)
    const float* __restrict__ in_proj_w,   // (3C, C): wv = rows [2C,3C)
    const float* __restrict__ in_proj_b,   // (3C,):   bv = [2C,3C)
    const float* __restrict__ kv_w,        // (2C, EMB): v-part = rows [C,2C)
    const float* __restrict__ kv_b)        // (2C,)
{
    const int b    = blockIdx.x / CLUSTER;            // batch (cluster id)
    const int rank = blockIdx.x % CLUSTER;            // block-in-cluster
    const int lane = threadIdx.x & 31;
    const int cw   = rank * 8 + (threadIdx.x >> 5);   // cluster-warp 0..63
    const int r0   = cw * 4;                          // 4 rows per warp

    // ---- Stage 1: t1[b][r0+j] = dot(kv_w_v[r0+j], ce[b]) + kv_b_v[r0+j] ----
    {
        const float4* __restrict__ ce =
            reinterpret_cast<const float4*>(cond_emb + (size_t)b * EMB_);
        const float4* __restrict__ w0 =
            reinterpret_cast<const float4*>(kv_w + (size_t)(C_ + r0 + 0) * EMB_);
        const float4* __restrict__ w1 =
            reinterpret_cast<const float4*>(kv_w + (size_t)(C_ + r0 + 1) * EMB_);
        const float4* __restrict__ w2 =
            reinterpret_cast<const float4*>(kv_w + (size_t)(C_ + r0 + 2) * EMB_);
        const float4* __restrict__ w3 =
            reinterpret_cast<const float4*>(kv_w + (size_t)(C_ + r0 + 3) * EMB_);

        float a0 = 0.f, a1 = 0.f, a2 = 0.f, a3 = 0.f;
        #pragma unroll
        for (int k = lane; k < EMB_ / 4; k += 32) {
            const float4 c = ce[k];
            const float4 q0 = w0[k], q1 = w1[k], q2 = w2[k], q3 = w3[k];
            a0 += q0.x * c.x + q0.y * c.y + q0.z * c.z + q0.w * c.w;
            a1 += q1.x * c.x + q1.y * c.y + q1.z * c.z + q1.w * c.w;
            a2 += q2.x * c.x + q2.y * c.y + q2.z * c.z + q2.w * c.w;
            a3 += q3.x * c.x + q3.y * c.y + q3.z * c.z + q3.w * c.w;
        }
        #pragma unroll
        for (int o = 16; o > 0; o >>= 1) {
            a0 += __shfl_down_sync(0xffffffffu, a0, o);
            a1 += __shfl_down_sync(0xffffffffu, a1, o);
            a2 += __shfl_down_sync(0xffffffffu, a2, o);
            a3 += __shfl_down_sync(0xffffffffu, a3, o);
        }
        if (lane == 0) {
            float* t1r = g_t1 + (size_t)b * C_ + r0;
            t1r[0] = a0 + kv_b[C_ + r0 + 0];
            t1r[1] = a1 + kv_b[C_ + r0 + 1];
            t1r[2] = a2 + kv_b[C_ + r0 + 2];
            t1r[3] = a3 + kv_b[C_ + r0 + 3];
        }
    }

    // ---- HW cluster barrier: all 8 blocks of this batch sync ----
    __threadfence();   // make t1 writes visible at device scope
    asm volatile("barrier.cluster.arrive.aligned;" ::: "memory");
    asm volatile("barrier.cluster.wait.aligned;"   ::: "memory");

    // ---- Stage 2: t2[b][r0+j] = dot(wv[r0+j], t1[b]) + bv[r0+j] ----
    {
        const float* __restrict__ wv = in_proj_w + (size_t)2 * C_ * C_;
        const float4* __restrict__ t1v =
            reinterpret_cast<const float4*>(g_t1 + (size_t)b * C_);
        const float4* __restrict__ w0 =
            reinterpret_cast<const float4*>(wv + (size_t)(r0 + 0) * C_);
        const float4* __restrict__ w1 =
            reinterpret_cast<const float4*>(wv + (size_t)(r0 + 1) * C_);
        const float4* __restrict__ w2 =
            reinterpret_cast<const float4*>(wv + (size_t)(r0 + 2) * C_);
        const float4* __restrict__ w3 =
            reinterpret_cast<const float4*>(wv + (size_t)(r0 + 3) * C_);

        float a0 = 0.f, a1 = 0.f, a2 = 0.f, a3 = 0.f;
        #pragma unroll
        for (int k = lane; k < C_ / 4; k += 32) {
            const float4 c = __ldcg(&t1v[k]);   // bypass L1: peer-block data
            const float4 q0 = w0[k], q1 = w1[k], q2 = w2[k], q3 = w3[k];
            a0 += q0.x * c.x + q0.y * c.y + q0.z * c.z + q0.w * c.w;
            a1 += q1.x * c.x + q1.y * c.y + q1.z * c.z + q1.w * c.w;
            a2 += q2.x * c.x + q2.y * c.y + q2.z * c.z + q2.w * c.w;
            a3 += q3.x * c.x + q3.y * c.y + q3.z * c.z + q3.w * c.w;
        }
        #pragma unroll
        for (int o = 16; o > 0; o >>= 1) {
            a0 += __shfl_down_sync(0xffffffffu, a0, o);
            a1 += __shfl_down_sync(0xffffffffu, a1, o);
            a2 += __shfl_down_sync(0xffffffffu, a2, o);
            a3 += __shfl_down_sync(0xffffffffu, a3, o);
        }
        if (lane == 0) {
            const float* __restrict__ bv = in_proj_b + 2 * C_;
            float* t2r = g_t2 + (size_t)b * C_ + r0;
            t2r[0] = a0 + bv[r0 + 0];
            t2r[1] = a1 + bv[r0 + 1];
            t2r[2] = a2 + bv[r0 + 2];
            t2r[3] = a3 + bv[r0 + 3];
        }
    }
}

// ---------------------------------------------------------------------------
// K2: stream kernel with inline stage 3 (R7-proven form, unchanged):
//   a       = dot(out_w[c,:], t2[b,:]) + out_b[c]
//   y[bc,:] = x[bc,:] + a
// ---------------------------------------------------------------------------
__global__ void __launch_bounds__(256) broadcast_add_kernel(
    const float* __restrict__ x,
    const float* __restrict__ out_w,   // (C_, C_)
    const float* __restrict__ out_b,   // (C_,)
    float* __restrict__ y)
{
    const int bc   = blockIdx.x;                 // 0 .. B*C-1
    const int b    = bc >> 8;
    const int c    = bc & (C_ - 1);
    const int tid  = threadIdx.x;
    const int lane = tid & 31;
    const int warp = tid >> 5;

    const float4* __restrict__ xi = reinterpret_cast<const float4*>(x) + (size_t)bc * (HW_ / 4);
    float4* __restrict__       yo = reinterpret_cast<float4*>(y)       + (size_t)bc * (HW_ / 4);

    // Streaming loads first; the dot hides beneath them.
    float4 v0 = xi[tid];
    float4 v1 = xi[tid + 256];
    float4 v2 = xi[tid + 512];
    float4 v3 = xi[tid + 768];

    float p = out_w[(size_t)c * C_ + tid] * g_t2[(size_t)b * C_ + tid];
    #pragma unroll
    for (int o = 16; o > 0; o >>= 1)
        p += __shfl_down_sync(0xffffffffu, p, o);

    __shared__ float s_part[8];
    __shared__ float s_a;
    if (lane == 0) s_part[warp] = p;
    __syncthreads();
    if (tid < 8) {
        float q = s_part[tid];
        q += __shfl_down_sync(0x000000ffu, q, 4);
        q += __shfl_down_sync(0x000000ffu, q, 2);
        q += __shfl_down_sync(0x000000ffu, q, 1);
        if (tid == 0) s_a = q + out_b[c];
    }
    __syncthreads();
    const float a = s_a;

    v0.x += a; v0.y += a; v0.z += a; v0.w += a;
    v1.x += a; v1.y += a; v1.z += a; v1.w += a;
    v2.x += a; v2.y += a; v2.z += a; v2.w += a;
    v3.x += a; v3.y += a; v3.z += a; v3.w += a;
    yo[tid]       = v0;
    yo[tid + 256] = v1;
    yo[tid + 512] = v2;
    yo[tid + 768] = v3;
}

extern "C" void kernel_launch(void* const* d_in, const int* in_sizes, int n_in,
                              void* d_out, int out_size)
{
    // metadata order: x, cond_emb, ln_gamma, ln_beta, in_proj_w, in_proj_b,
    //                 out_w, out_b, kv_w, kv_b
    const float* x         = (const float*)d_in[0];
    const float* cond_emb  = (const float*)d_in[1];
    // ln_gamma/ln_beta provably do not affect the output: softmax over the
    // size-1 KV axis is exactly 1, so q (and thus x_ln) cancels.
    const float* in_proj_w = (const float*)d_in[4];
    const float* in_proj_b = (const float*)d_in[5];
    const float* out_w     = (const float*)d_in[6];
    const float* out_b     = (const float*)d_in[7];
    const float* kv_w      = (const float*)d_in[8];
    const float* kv_b      = (const float*)d_in[9];
    float* y = (float*)d_out;

    chain_cluster_kernel<<<CHAIN_BLOCKS, 256>>>(cond_emb, in_proj_w, in_proj_b,
                                                kv_w, kv_b);
    broadcast_add_kernel<<<B_ * C_, 256>>>(x, out_w, out_b, y);
}

// round 13
// speedup vs baseline: 1.1394x; 1.0080x over previous
#include <cuda_runtime.h>

// Problem constants
#define B_   64
#define C_   256
#define HW_  4096
#define EMB_ 512
#define CLUSTER 8                    // blocks per cluster; 1 cluster = 1 batch
#define CHAIN_BLOCKS (B_ * CLUSTER)  // 512

// Scratch (allocation-free rule: __device__ globals)
__device__ float g_t1[B_ * C_];
__device__ float g_t2[B_ * C_];

// ---------------------------------------------------------------------------
// K1: stage1 + stage2 in ONE launch (HW cluster barrier), with stage2's
// weights PREFETCHED INTO REGISTERS BEFORE stage1 so the two cold DRAM
// weight fetches (kv_w_v 512KB, wv 256KB) overlap instead of serializing.
// Cluster c (8 blocks x 64 warps) owns batch b = c; warp w owns rows 4w..4w+3.
// ---------------------------------------------------------------------------
__global__ void __launch_bounds__(256) __cluster_dims__(CLUSTER, 1, 1)
chain_cluster_kernel(
    const float* __restrict__ cond_emb,    // (B, EMB)
    const float* __restrict__ in_proj_w,   // (3C, C): wv = rows [2C,3C)
    const float* __restrict__ in_proj_b,   // (3C,):   bv = [2C,3C)
    const float* __restrict__ kv_w,        // (2C, EMB): v-part = rows [C,2C)
    const float* __restrict__ kv_b)        // (2C,)
{
    const int b    = blockIdx.x / CLUSTER;            // batch (cluster id)
    const int rank = blockIdx.x % CLUSTER;            // block-in-cluster
    const int lane = threadIdx.x & 31;
    const int cw   = rank * 8 + (threadIdx.x >> 5);   // cluster-warp 0..63
    const int r0   = cw * 4;                          // 4 rows per warp

    // ---- Prefetch stage2 weights (wv rows r0..r0+3) into registers NOW.
    //      These loads do not depend on anything; issuing them first lets
    //      their DRAM fetch overlap stage1's weight fetch below. ----
    const float* __restrict__ wv = in_proj_w + (size_t)2 * C_ * C_;
    float4 wreg[8];
    #pragma unroll
    for (int j = 0; j < 4; j++) {
        const float4* wr = reinterpret_cast<const float4*>(wv + (size_t)(r0 + j) * C_);
        wreg[2 * j]     = wr[lane];
        wreg[2 * j + 1] = wr[lane + 32];
    }

    // ---- Stage 1: t1[b][r0+j] = dot(kv_w_v[r0+j], ce[b]) + kv_b_v[r0+j] ----
    {
        const float4* __restrict__ ce =
            reinterpret_cast<const float4*>(cond_emb + (size_t)b * EMB_);
        const float4* __restrict__ w0 =
            reinterpret_cast<const float4*>(kv_w + (size_t)(C_ + r0 + 0) * EMB_);
        const float4* __restrict__ w1 =
            reinterpret_cast<const float4*>(kv_w + (size_t)(C_ + r0 + 1) * EMB_);
        const float4* __restrict__ w2 =
            reinterpret_cast<const float4*>(kv_w + (size_t)(C_ + r0 + 2) * EMB_);
        const float4* __restrict__ w3 =
            reinterpret_cast<const float4*>(kv_w + (size_t)(C_ + r0 + 3) * EMB_);

        float a0 = 0.f, a1 = 0.f, a2 = 0.f, a3 = 0.f;
        #pragma unroll
        for (int k = lane; k < EMB_ / 4; k += 32) {
            const float4 c = ce[k];
            const float4 q0 = w0[k], q1 = w1[k], q2 = w2[k], q3 = w3[k];
            a0 += q0.x * c.x + q0.y * c.y + q0.z * c.z + q0.w * c.w;
            a1 += q1.x * c.x + q1.y * c.y + q1.z * c.z + q1.w * c.w;
            a2 += q2.x * c.x + q2.y * c.y + q2.z * c.z + q2.w * c.w;
            a3 += q3.x * c.x + q3.y * c.y + q3.z * c.z + q3.w * c.w;
        }
        #pragma unroll
        for (int o = 16; o > 0; o >>= 1) {
            a0 += __shfl_down_sync(0xffffffffu, a0, o);
            a1 += __shfl_down_sync(0xffffffffu, a1, o);
            a2 += __shfl_down_sync(0xffffffffu, a2, o);
            a3 += __shfl_down_sync(0xffffffffu, a3, o);
        }
        if (lane == 0) {
            float* t1r = g_t1 + (size_t)b * C_ + r0;
            t1r[0] = a0 + kv_b[C_ + r0 + 0];
            t1r[1] = a1 + kv_b[C_ + r0 + 1];
            t1r[2] = a2 + kv_b[C_ + r0 + 2];
            t1r[3] = a3 + kv_b[C_ + r0 + 3];
        }
    }

    // ---- HW cluster barrier: all 8 blocks of this batch sync ----
    __threadfence();   // make t1 writes visible at device scope
    asm volatile("barrier.cluster.arrive.aligned;" ::: "memory");
    asm volatile("barrier.cluster.wait.aligned;"   ::: "memory");

    // ---- Stage 2: t2[b][r0+j] = dot(wv[r0+j], t1[b]) + bv[r0+j]
    //      wv already in registers; t1 reads are L2 hits. Fast. ----
    {
        const float4* __restrict__ t1v =
            reinterpret_cast<const float4*>(g_t1 + (size_t)b * C_);
        const float4 tA = __ldcg(&t1v[lane]);        // bypass L1: peer-block data
        const float4 tB = __ldcg(&t1v[lane + 32]);

        float acc[4];
        #pragma unroll
        for (int j = 0; j < 4; j++) {
            const float4 wA = wreg[2 * j], wB = wreg[2 * j + 1];
            acc[j] = wA.x * tA.x + wA.y * tA.y + wA.z * tA.z + wA.w * tA.w
                   + wB.x * tB.x + wB.y * tB.y + wB.z * tB.z + wB.w * tB.w;
            #pragma unroll
            for (int o = 16; o > 0; o >>= 1)
                acc[j] += __shfl_down_sync(0xffffffffu, acc[j], o);
        }
        if (lane == 0) {
            const float* __restrict__ bv = in_proj_b + 2 * C_;
            float* t2r = g_t2 + (size_t)b * C_ + r0;
            #pragma unroll
            for (int j = 0; j < 4; j++)
                t2r[j] = acc[j] + bv[r0 + j];
        }
    }
}

// ---------------------------------------------------------------------------
// K2: stream kernel with inline stage 3 (R7-proven form, unchanged):
//   a       = dot(out_w[c,:], t2[b,:]) + out_b[c]
//   y[bc,:] = x[bc,:] + a
// ---------------------------------------------------------------------------
__global__ void __launch_bounds__(256) broadcast_add_kernel(
    const float* __restrict__ x,
    const float* __restrict__ out_w,   // (C_, C_)
    const float* __restrict__ out_b,   // (C_,)
    float* __restrict__ y)
{
    const int bc   = blockIdx.x;                 // 0 .. B*C-1
    const int b    = bc >> 8;
    const int c    = bc & (C_ - 1);
    const int tid  = threadIdx.x;
    const int lane = tid & 31;
    const int warp = tid >> 5;

    const float4* __restrict__ xi = reinterpret_cast<const float4*>(x) + (size_t)bc * (HW_ / 4);
    float4* __restrict__       yo = reinterpret_cast<float4*>(y)       + (size_t)bc * (HW_ / 4);

    // Streaming loads first; the dot hides beneath them.
    float4 v0 = xi[tid];
    float4 v1 = xi[tid + 256];
    float4 v2 = xi[tid + 512];
    float4 v3 = xi[tid + 768];

    float p = out_w[(size_t)c * C_ + tid] * g_t2[(size_t)b * C_ + tid];
    #pragma unroll
    for (int o = 16; o > 0; o >>= 1)
        p += __shfl_down_sync(0xffffffffu, p, o);

    __shared__ float s_part[8];
    __shared__ float s_a;
    if (lane == 0) s_part[warp] = p;
    __syncthreads();
    if (tid < 8) {
        float q = s_part[tid];
        q += __shfl_down_sync(0x000000ffu, q, 4);
        q += __shfl_down_sync(0x000000ffu, q, 2);
        q += __shfl_down_sync(0x000000ffu, q, 1);
        if (tid == 0) s_a = q + out_b[c];
    }
    __syncthreads();
    const float a = s_a;

    v0.x += a; v0.y += a; v0.z += a; v0.w += a;
    v1.x += a; v1.y += a; v1.z += a; v1.w += a;
    v2.x += a; v2.y += a; v2.z += a; v2.w += a;
    v3.x += a; v3.y += a; v3.z += a; v3.w += a;
    yo[tid]       = v0;
    yo[tid + 256] = v1;
    yo[tid + 512] = v2;
    yo[tid + 768] = v3;
}

extern "C" void kernel_launch(void* const* d_in, const int* in_sizes, int n_in,
                              void* d_out, int out_size)
{
    // metadata order: x, cond_emb, ln_gamma, ln_beta, in_proj_w, in_proj_b,
    //                 out_w, out_b, kv_w, kv_b
    const float* x         = (const float*)d_in[0];
    const float* cond_emb  = (const float*)d_in[1];
    // ln_gamma/ln_beta provably do not affect the output: softmax over the
    // size-1 KV axis is exactly 1, so q (and thus x_ln) cancels.
    const float* in_proj_w = (const float*)d_in[4];
    const float* in_proj_b = (const float*)d_in[5];
    const float* out_w     = (const float*)d_in[6];
    const float* out_b     = (const float*)d_in[7];
    const float* kv_w      = (const float*)d_in[8];
    const float* kv_b      = (const float*)d_in[9];
    float* y = (float*)d_out;

    chain_cluster_kernel<<<CHAIN_BLOCKS, 256>>>(cond_emb, in_proj_w, in_proj_b,
                                                kv_w, kv_b);
    broadcast_add_kernel<<<B_ * C_, 256>>>(x, out_w, out_b, y);
}